// round 2
// baseline (speedup 1.0000x reference)
#include <cuda_runtime.h>
#include <cuda_bf16.h>

#define NN 1024
#define DIM 128
#define HH 4
#define DD 32
#define I_TILE 8

// Scratch (device globals: no allocations allowed)
__device__ float g_L[NN * DIM];
__device__ float g_R[NN * DIM];
__device__ float g_V[NN * DIM];
__device__ float g_La6[NN * HH];
__device__ float g_Ra6[NN * HH];

// ---------------------------------------------------------------------------
// Prep: L = h@W_l, R = h@W_r, V = h@W_v, plus La6[i,h]=0.6*sum_d a_d*L[i,h,d]
// (and Ra6 from R). Grid (64, 3), block 128. Each CTA: 16 rows x 128 cols.
// ---------------------------------------------------------------------------
__global__ __launch_bounds__(128) void prep_kernel(
    const float* __restrict__ h,
    const float* __restrict__ Wl,
    const float* __restrict__ Wr,
    const float* __restrict__ Wv,
    const float* __restrict__ a)
{
    int which = blockIdx.y;
    const float* W = (which == 0) ? Wl : (which == 1) ? Wr : Wv;
    float* outp    = (which == 0) ? g_L : (which == 1) ? g_R : g_V;
    int i0 = blockIdx.x * 16;
    int tid = threadIdx.x;

    __shared__ float h_s[16 * DIM];
    for (int idx = tid; idx < 16 * DIM; idx += 128)
        h_s[idx] = h[i0 * DIM + idx];
    __syncthreads();

    float acc[16];
#pragma unroll
    for (int r = 0; r < 16; r++) acc[r] = 0.f;

    for (int k = 0; k < DIM; k++) {
        float wv = W[k * DIM + tid];
#pragma unroll
        for (int r = 0; r < 16; r++) acc[r] += h_s[r * DIM + k] * wv;
    }

#pragma unroll
    for (int r = 0; r < 16; r++) outp[(i0 + r) * DIM + tid] = acc[r];

    if (which < 2) {
        int lane = tid & 31, head = tid >> 5;      // 128 threads: warp == head
        float av = 0.6f * __ldg(&a[lane]);
        float* A6 = (which == 0) ? g_La6 : g_Ra6;
#pragma unroll
        for (int r = 0; r < 16; r++) {
            float v = av * acc[r];
#pragma unroll
            for (int o = 16; o; o >>= 1) v += __shfl_xor_sync(0xffffffffu, v, o);
            if (lane == 0) A6[(i0 + r) * HH + head] = v;
        }
    }
}

// ---------------------------------------------------------------------------
// Main fused kernel: pairwise scores + masked (max-free) softmax + aggregation
// + LayerNorm + ReLU.
// Grid 128 (I_TILE=8 rows each), block 256 = 8 warps.
// warp w handles head (w&3), i-half (w>>2): 4 i-rows per warp.
// e-phase: lane owns j (32 j per tile). agg-phase: lane owns d.
// ---------------------------------------------------------------------------
__global__ __launch_bounds__(256) void gat_main(
    const int*   __restrict__ adj,
    const float* __restrict__ a,
    const float* __restrict__ ln_g,
    const float* __restrict__ ln_b,
    float*       __restrict__ out)
{
    int tid  = threadIdx.x;
    int w    = tid >> 5, lane = tid & 31;
    int head = w & 3,    ih   = w >> 2;      // ih in {0,1}
    int i0   = blockIdx.x * I_TILE;

    __shared__ float l_s[I_TILE * DIM];      // also reused as agg buffer at end
    __shared__ float r_s[32 * 129];          // pad 129: conflict-free
    __shared__ float v_s[32 * 129];
    __shared__ int   adj_s[I_TILE * 32];
    __shared__ float p_s[8][4][32];          // [warp][ii][j]

    // 0.4 * a_d in registers (the |.| term weight)
    float ar[32];
#pragma unroll
    for (int d = 0; d < 32; d++) ar[d] = 0.4f * __ldg(&a[d]);

    // stage l rows for this CTA
    for (int idx = tid; idx < I_TILE * DIM; idx += 256)
        l_s[idx] = g_L[i0 * DIM + idx];

    float la[4], sl[4], accA[4];
#pragma unroll
    for (int ii = 0; ii < 4; ii++) {
        la[ii]   = __ldg(&g_La6[(i0 + ih * 4 + ii) * HH + head]);
        sl[ii]   = 0.f;
        accA[ii] = 0.f;
    }

    for (int t = 0; t < NN / 32; t++) {
        int j0 = t * 32;
        __syncthreads();   // previous tile fully consumed (and l_s staged, 1st iter)

        // stage r/v tile: 32 rows x 128 cols, float4 loads, coalesced
#pragma unroll
        for (int q = 0; q < 4; q++) {
            int idx = tid + q * 256;                 // 1024 float4 slots
            int row = idx >> 5, c4 = (idx & 31) * 4;
            float4 rv = *reinterpret_cast<const float4*>(&g_R[(j0 + row) * DIM + c4]);
            float4 vv = *reinterpret_cast<const float4*>(&g_V[(j0 + row) * DIM + c4]);
            float* dr = &r_s[row * 129 + c4];
            dr[0] = rv.x; dr[1] = rv.y; dr[2] = rv.z; dr[3] = rv.w;
            float* dv = &v_s[row * 129 + c4];
            dv[0] = vv.x; dv[1] = vv.y; dv[2] = vv.z; dv[3] = vv.w;
        }
        adj_s[tid] = adj[(i0 + (tid >> 5)) * NN + j0 + (tid & 31)]; // 256 == blockDim
        __syncthreads();

        // lane owns j = j0+lane: pull its r-vector (head slice) into registers
        float r_reg[32];
#pragma unroll
        for (int d = 0; d < 32; d++) r_reg[d] = r_s[lane * 129 + head * 32 + d];
        float ra = __ldg(&g_Ra6[(j0 + lane) * HH + head]);

        // ---- e phase: p = mask ? exp(e) : 0 (max-free softmax) ----
#pragma unroll
        for (int ii = 0; ii < 4; ii++) {
            int i = ih * 4 + ii;
            const float2* lp = reinterpret_cast<const float2*>(&l_s[i * DIM + head * 32]);
            float a0 = 0.f, a1 = 0.f, a2 = 0.f, a3 = 0.f;
#pragma unroll
            for (int q = 0; q < 8; q++) {
                float2 x = lp[2 * q], y = lp[2 * q + 1];
                a0 += ar[4 * q + 0] * fabsf(x.x + r_reg[4 * q + 0]);
                a1 += ar[4 * q + 1] * fabsf(x.y + r_reg[4 * q + 1]);
                a2 += ar[4 * q + 2] * fabsf(y.x + r_reg[4 * q + 2]);
                a3 += ar[4 * q + 3] * fabsf(y.y + r_reg[4 * q + 3]);
            }
            float e = la[ii] + ra + ((a0 + a1) + (a2 + a3));
            float p = adj_s[i * 32 + lane] ? __expf(e) : 0.f;
            sl[ii] += p;
            p_s[w][ii][lane] = p;
        }
        __syncwarp();

        // ---- agg phase: lane owns d, accumulate p_j * v_j[d] ----
#pragma unroll
        for (int ii = 0; ii < 4; ii++) {
            float c0 = 0.f, c1 = 0.f, c2 = 0.f, c3 = 0.f;
            const float* vp = &v_s[head * 32 + lane];
#pragma unroll
            for (int q = 0; q < 8; q++) {
                float4 p4 = *reinterpret_cast<const float4*>(&p_s[w][ii][q * 4]);
                c0 += p4.x * vp[(q * 4 + 0) * 129];
                c1 += p4.y * vp[(q * 4 + 1) * 129];
                c2 += p4.z * vp[(q * 4 + 2) * 129];
                c3 += p4.w * vp[(q * 4 + 3) * 129];
            }
            accA[ii] += (c0 + c1) + (c2 + c3);
        }
        __syncwarp();
    }

    // normalize and stash agg rows (reuse l_s)
    __syncthreads();
#pragma unroll
    for (int ii = 0; ii < 4; ii++) {
        float S = sl[ii];
#pragma unroll
        for (int o = 16; o; o >>= 1) S += __shfl_xor_sync(0xffffffffu, S, o);
        l_s[(ih * 4 + ii) * DIM + head * 32 + lane] = accA[ii] * (1.0f / S);
    }
    __syncthreads();

    // LayerNorm + ReLU: warp w handles row i = w (8 warps, 8 rows)
    {
        int i = w;
        float v0 = l_s[i * DIM + lane];
        float v1 = l_s[i * DIM + 32 + lane];
        float v2 = l_s[i * DIM + 64 + lane];
        float v3 = l_s[i * DIM + 96 + lane];
        float sm = (v0 + v1) + (v2 + v3);
        float sq = v0 * v0 + v1 * v1 + v2 * v2 + v3 * v3;
#pragma unroll
        for (int o = 16; o; o >>= 1) {
            sm += __shfl_xor_sync(0xffffffffu, sm, o);
            sq += __shfl_xor_sync(0xffffffffu, sq, o);
        }
        float mean = sm * (1.f / 128.f);
        float var  = sq * (1.f / 128.f) - mean * mean;
        float rstd = rsqrtf(var + 1e-5f);
        float vals[4] = {v0, v1, v2, v3};
#pragma unroll
        for (int k = 0; k < 4; k++) {
            int c = 32 * k + lane;
            float y = (vals[k] - mean) * rstd * __ldg(&ln_g[c]) + __ldg(&ln_b[c]);
            out[(i0 + i) * DIM + c] = fmaxf(y, 0.f);
        }
    }
}

extern "C" void kernel_launch(void* const* d_in, const int* in_sizes, int n_in,
                              void* d_out, int out_size)
{
    const float* h   = (const float*)d_in[0];
    const int*   adj = (const int*)  d_in[1];
    const float* Wl  = (const float*)d_in[2];
    const float* Wr  = (const float*)d_in[3];
    const float* Wv  = (const float*)d_in[4];
    const float* a   = (const float*)d_in[5];
    const float* g   = (const float*)d_in[6];
    const float* b   = (const float*)d_in[7];

    prep_kernel<<<dim3(64, 3), 128>>>(h, Wl, Wr, Wv, a);
    gat_main<<<NN / I_TILE, 256>>>(adj, a, g, b, (float*)d_out);
}

// round 4
// speedup vs baseline: 1.1715x; 1.1715x over previous
#include <cuda_runtime.h>
#include <cuda_bf16.h>

#define NN 1024
#define DIM 128
#define HH 4
#define DD 32
#define I_TILE 8
#define J_STAGE 128
#define PITCH 132          // floats per staged row; 132%32==4 -> conflict-free f4 & scalar

// Scratch (device globals: no allocations allowed)
__device__ float g_L[NN * DIM];
__device__ float g_R[NN * DIM];
__device__ float g_V[NN * DIM];
__device__ float g_La6[NN * HH];
__device__ float g_Ra6[NN * HH];

// ---------------------------------------------------------------------------
// Prep: L = h@W_l, R = h@W_r, V = h@W_v, plus La6[i,h]=0.6*sum_d a_d*L[i,h,d]
// (and Ra6 from R). Grid (128, 3), block 128. Each CTA: 8 rows x 128 cols.
// ---------------------------------------------------------------------------
__global__ __launch_bounds__(128) void prep_kernel(
    const float* __restrict__ h,
    const float* __restrict__ Wl,
    const float* __restrict__ Wr,
    const float* __restrict__ Wv,
    const float* __restrict__ a)
{
    int which = blockIdx.y;
    const float* W = (which == 0) ? Wl : (which == 1) ? Wr : Wv;
    float* outp    = (which == 0) ? g_L : (which == 1) ? g_R : g_V;
    int i0 = blockIdx.x * 8;
    int tid = threadIdx.x;

    __shared__ float h_s[8 * DIM];
#pragma unroll
    for (int q = 0; q < 8; q++)
        h_s[tid + q * 128] = h[i0 * DIM + tid + q * 128];
    __syncthreads();

    float acc[8];
#pragma unroll
    for (int r = 0; r < 8; r++) acc[r] = 0.f;

    const float4* h4 = reinterpret_cast<const float4*>(h_s);
#pragma unroll 4
    for (int k4 = 0; k4 < 32; k4++) {
        float w0 = W[(k4 * 4 + 0) * DIM + tid];
        float w1 = W[(k4 * 4 + 1) * DIM + tid];
        float w2 = W[(k4 * 4 + 2) * DIM + tid];
        float w3 = W[(k4 * 4 + 3) * DIM + tid];
#pragma unroll
        for (int r = 0; r < 8; r++) {
            float4 hv = h4[r * 32 + k4];
            acc[r] += hv.x * w0 + hv.y * w1 + hv.z * w2 + hv.w * w3;
        }
    }

#pragma unroll
    for (int r = 0; r < 8; r++) outp[(i0 + r) * DIM + tid] = acc[r];

    if (which < 2) {
        int lane = tid & 31, head = tid >> 5;      // warp == head
        float av = 0.6f * __ldg(&a[lane]);
        float* A6 = (which == 0) ? g_La6 : g_Ra6;
#pragma unroll
        for (int r = 0; r < 8; r++) {
            float v = av * acc[r];
#pragma unroll
            for (int o = 16; o; o >>= 1) v += __shfl_xor_sync(0xffffffffu, v, o);
            if (lane == 0) A6[(i0 + r) * HH + head] = v;
        }
    }
}

// ---------------------------------------------------------------------------
// Main fused kernel. Grid 128 (I_TILE=8 rows each), block 512 = 16 warps.
// Warp w: head = w&3, js = w>>2. Each warp handles its 32-j subtile of the
// staged 128 j, for ALL 8 i-rows (amortizes r_reg + v reads over rows).
// e-phase: lane owns j. agg-phase: lane owns d. p handed off via smem.
// Max-free softmax (e is O(1) bounded); mask -> p = 0 directly.
// ---------------------------------------------------------------------------
__global__ __launch_bounds__(512) void gat_main(
    const int*   __restrict__ adj,
    const float* __restrict__ a,
    const float* __restrict__ ln_g,
    const float* __restrict__ ln_b,
    float*       __restrict__ out)
{
    extern __shared__ float smem[];
    float* r_s  = smem;                          // [128][PITCH]
    float* v_s  = r_s + J_STAGE * PITCH;         // [128][PITCH]
    float* l_s  = v_s + J_STAGE * PITCH;         // [8][128] (later: out buffer)
    float* p_s  = l_s + I_TILE * DIM;            // [16][8][32] (later: acc red)
    float* sl_s = p_s + 16 * 8 * 32;             // [16][8]
    float* la_s = sl_s + 16 * 8;                 // [8][4]
    int*   adj_s = reinterpret_cast<int*>(la_s + I_TILE * HH); // [8][128]

    int tid  = threadIdx.x;
    int w    = tid >> 5, lane = tid & 31;
    int head = w & 3,    js   = w >> 2;          // js in 0..3
    int i0   = blockIdx.x * I_TILE;

    // 0.4 * a_d in registers
    float ar[32];
#pragma unroll
    for (int d = 0; d < 32; d++) ar[d] = 0.4f * __ldg(&a[d]);

    // stage l rows + la for this CTA
    for (int idx = tid; idx < I_TILE * DIM; idx += 512)
        l_s[idx] = g_L[i0 * DIM + idx];
    if (tid < I_TILE * HH)
        la_s[tid] = g_La6[i0 * HH + tid];

    float sl[I_TILE], accA[I_TILE];
#pragma unroll
    for (int ii = 0; ii < I_TILE; ii++) { sl[ii] = 0.f; accA[ii] = 0.f; }

    for (int t = 0; t < NN / J_STAGE; t++) {
        int j0 = t * J_STAGE;
        __syncthreads();   // previous stage fully consumed (covers l_s 1st iter)

        // stage r/v: 128 rows x 128 floats each. warp w writes rows w, w+16,...
#pragma unroll
        for (int q = 0; q < 8; q++) {
            int row = w + 16 * q;
            float4 rv = *reinterpret_cast<const float4*>(&g_R[(j0 + row) * DIM + lane * 4]);
            float4 vv = *reinterpret_cast<const float4*>(&g_V[(j0 + row) * DIM + lane * 4]);
            *reinterpret_cast<float4*>(&r_s[row * PITCH + lane * 4]) = rv;
            *reinterpret_cast<float4*>(&v_s[row * PITCH + lane * 4]) = vv;
        }
        adj_s[tid]       = adj[(i0 + (tid >> 7)) * NN + j0 + (tid & 127)];
        adj_s[tid + 512] = adj[(i0 + 4 + (tid >> 7)) * NN + j0 + (tid & 127)];
        __syncthreads();

        // warp's j-range: local rows js*32 .. js*32+31; lane owns one j
        int jr = js * 32 + lane;
        float r_reg[32];
#pragma unroll
        for (int q = 0; q < 8; q++) {
            float4 r4 = *reinterpret_cast<const float4*>(&r_s[jr * PITCH + head * 32 + q * 4]);
            r_reg[q * 4 + 0] = r4.x; r_reg[q * 4 + 1] = r4.y;
            r_reg[q * 4 + 2] = r4.z; r_reg[q * 4 + 3] = r4.w;
        }
        float ra = __ldg(&g_Ra6[(j0 + jr) * HH + head]);

        // ---- e phase over all 8 rows ----
#pragma unroll
        for (int ii = 0; ii < I_TILE; ii++) {
            const float4* lp = reinterpret_cast<const float4*>(&l_s[ii * DIM + head * 32]);
            float a0 = 0.f, a1 = 0.f, a2 = 0.f, a3 = 0.f;
#pragma unroll
            for (int q = 0; q < 8; q++) {
                float4 l4 = lp[q];
                a0 += ar[4 * q + 0] * fabsf(l4.x + r_reg[4 * q + 0]);
                a1 += ar[4 * q + 1] * fabsf(l4.y + r_reg[4 * q + 1]);
                a2 += ar[4 * q + 2] * fabsf(l4.z + r_reg[4 * q + 2]);
                a3 += ar[4 * q + 3] * fabsf(l4.w + r_reg[4 * q + 3]);
            }
            float e = la_s[ii * HH + head] + ra + ((a0 + a1) + (a2 + a3));
            float p = adj_s[ii * J_STAGE + jr] ? __expf(e) : 0.f;
            sl[ii] += p;
            p_s[(w * 8 + ii) * 32 + lane] = p;
        }
        __syncwarp();

        // ---- agg phase: lane owns d; v hoisted, reused across all ii ----
#pragma unroll
        for (int q = 0; q < 4; q++) {
            int jrow = js * 32 + q * 8;
            const float* vp = &v_s[jrow * PITCH + head * 32 + lane];
            float v0 = vp[0 * PITCH], v1 = vp[1 * PITCH], v2 = vp[2 * PITCH], v3 = vp[3 * PITCH];
            float v4 = vp[4 * PITCH], v5 = vp[5 * PITCH], v6 = vp[6 * PITCH], v7 = vp[7 * PITCH];
#pragma unroll
            for (int ii = 0; ii < I_TILE; ii++) {
                const float4* pp = reinterpret_cast<const float4*>(&p_s[(w * 8 + ii) * 32 + q * 8]);
                float4 pA = pp[0], pB = pp[1];
                accA[ii] += pA.x * v0 + pA.y * v1 + pA.z * v2 + pA.w * v3
                          + pB.x * v4 + pB.y * v5 + pB.z * v6 + pB.w * v7;
            }
        }
        __syncwarp();
    }

    // ---- cross-warp (js) reduction ----
    // warp-local lane reduction of sl
#pragma unroll
    for (int ii = 0; ii < I_TILE; ii++) {
        float S = sl[ii];
#pragma unroll
        for (int o = 16; o; o >>= 1) S += __shfl_xor_sync(0xffffffffu, S, o);
        sl[ii] = S;
    }
    __syncthreads();                 // everyone done reading p_s / v_s
#pragma unroll
    for (int ii = 0; ii < I_TILE; ii++) {
        p_s[(w * 8 + ii) * 32 + lane] = accA[ii];   // reuse p_s as acc buffer
        if (lane == 0) sl_s[w * 8 + ii] = sl[ii];
    }
    __syncthreads();

    // warp w: head' = w&3, covers ii = (w>>2) and (w>>2)+4
#pragma unroll
    for (int r = 0; r < 2; r++) {
        int ii = (w >> 2) + r * 4;
        int hh = w & 3;
        float acc = 0.f, S = 0.f;
#pragma unroll
        for (int g = 0; g < 4; g++) {
            acc += p_s[((g * 4 + hh) * 8 + ii) * 32 + lane];
            S   += sl_s[(g * 4 + hh) * 8 + ii];
        }
        l_s[ii * DIM + hh * 32 + lane] = acc * __frcp_rn(S);
    }
    __syncthreads();

    // LayerNorm + ReLU: warps 0..7 handle rows 0..7
    if (w < I_TILE) {
        int i = w;
        float v0 = l_s[i * DIM + lane];
        float v1 = l_s[i * DIM + 32 + lane];
        float v2 = l_s[i * DIM + 64 + lane];
        float v3 = l_s[i * DIM + 96 + lane];
        float sm = (v0 + v1) + (v2 + v3);
        float sq = v0 * v0 + v1 * v1 + v2 * v2 + v3 * v3;
#pragma unroll
        for (int o = 16; o; o >>= 1) {
            sm += __shfl_xor_sync(0xffffffffu, sm, o);
            sq += __shfl_xor_sync(0xffffffffu, sq, o);
        }
        float mean = sm * (1.f / 128.f);
        float var  = sq * (1.f / 128.f) - mean * mean;
        float rstd = rsqrtf(var + 1e-5f);
        float vals[4] = {v0, v1, v2, v3};
#pragma unroll
        for (int k = 0; k < 4; k++) {
            int c = 32 * k + lane;
            float y = (vals[k] - mean) * rstd * __ldg(&ln_g[c]) + __ldg(&ln_b[c]);
            out[(i0 + i) * DIM + c] = fmaxf(y, 0.f);
        }
    }
}

extern "C" void kernel_launch(void* const* d_in, const int* in_sizes, int n_in,
                              void* d_out, int out_size)
{
    const float* h   = (const float*)d_in[0];
    const int*   adj = (const int*)  d_in[1];
    const float* Wl  = (const float*)d_in[2];
    const float* Wr  = (const float*)d_in[3];
    const float* Wv  = (const float*)d_in[4];
    const float* a   = (const float*)d_in[5];
    const float* g   = (const float*)d_in[6];
    const float* b   = (const float*)d_in[7];

    const int smem_bytes =
        (2 * J_STAGE * PITCH + I_TILE * DIM + 16 * 8 * 32 + 16 * 8 + I_TILE * HH) * 4
        + I_TILE * J_STAGE * 4;

    static int configured = 0;
    if (!configured) {
        cudaFuncSetAttribute(gat_main, cudaFuncAttributeMaxDynamicSharedMemorySize, smem_bytes);
        configured = 1;
    }

    prep_kernel<<<dim3(128, 3), 128>>>(h, Wl, Wr, Wv, a);
    gat_main<<<NN / I_TILE, 512, smem_bytes>>>(adj, a, g, b, (float*)d_out);
}

// round 6
// speedup vs baseline: 2.2674x; 1.9355x over previous
#include <cuda_runtime.h>
#include <cuda_bf16.h>

#define NN 1024
#define DIM 128
#define HH 4
#define I_TILE 8

// Scratch (device globals: no allocations allowed)
__device__ float g_L[NN * DIM];
__device__ float g_Rt[NN * DIM];   // transposed: [head][q][j][4], d = q*4+c
__device__ float g_V[NN * DIM];
__device__ float g_La6[NN * HH];
__device__ float g_Ra6[NN * HH];

// ---------------------------------------------------------------------------
// Prep: L = h@W_l (row-major), Rt = transposed h@W_r, V = h@W_v, plus
// La6[i,h] = 0.6*sum_d a_d*L[i,h,d] (and Ra6 from R).
// Grid (128, 3), block 128. Each CTA: 8 rows x 128 cols.
// ---------------------------------------------------------------------------
__global__ __launch_bounds__(128) void prep_kernel(
    const float* __restrict__ h,
    const float* __restrict__ Wl,
    const float* __restrict__ Wr,
    const float* __restrict__ Wv,
    const float* __restrict__ a)
{
    int which = blockIdx.y;
    const float* W = (which == 0) ? Wl : (which == 1) ? Wr : Wv;
    int i0 = blockIdx.x * 8;
    int tid = threadIdx.x;

    __shared__ float h_s[8 * DIM];
#pragma unroll
    for (int q = 0; q < 8; q++)
        h_s[tid + q * 128] = h[i0 * DIM + tid + q * 128];
    __syncthreads();

    float acc[8];
#pragma unroll
    for (int r = 0; r < 8; r++) acc[r] = 0.f;

    const float4* h4 = reinterpret_cast<const float4*>(h_s);
#pragma unroll 4
    for (int k4 = 0; k4 < 32; k4++) {
        float w0 = __ldg(&W[(k4 * 4 + 0) * DIM + tid]);
        float w1 = __ldg(&W[(k4 * 4 + 1) * DIM + tid]);
        float w2 = __ldg(&W[(k4 * 4 + 2) * DIM + tid]);
        float w3 = __ldg(&W[(k4 * 4 + 3) * DIM + tid]);
#pragma unroll
        for (int r = 0; r < 8; r++) {
            float4 hv = h4[r * 32 + k4];
            acc[r] += hv.x * w0 + hv.y * w1 + hv.z * w2 + hv.w * w3;
        }
    }

    if (which == 1) {
        // transposed store: element (i0+r, col=tid) -> g_Rt[((head*8+q)*NN + i)*4 + c]
        int head = tid >> 5, dq = tid & 31, q = dq >> 2, c = dq & 3;
        float* base = &g_Rt[(size_t)((head * 8 + q) * NN) * 4 + c];
#pragma unroll
        for (int r = 0; r < 8; r++) base[(i0 + r) * 4] = acc[r];
    } else {
        float* outp = (which == 0) ? g_L : g_V;
#pragma unroll
        for (int r = 0; r < 8; r++) outp[(i0 + r) * DIM + tid] = acc[r];
    }

    if (which < 2) {
        int lane = tid & 31, head = tid >> 5;      // warp == head
        float av = 0.6f * __ldg(&a[lane]);
        float* A6 = (which == 0) ? g_La6 : g_Ra6;
#pragma unroll
        for (int r = 0; r < 8; r++) {
            float v = av * acc[r];
#pragma unroll
            for (int o = 16; o; o >>= 1) v += __shfl_xor_sync(0xffffffffu, v, o);
            if (lane == 0) A6[(i0 + r) * HH + head] = v;
        }
    }
}

// ---------------------------------------------------------------------------
// Main fused kernel. Grid 128 (I_TILE=8 rows each), block 512 = 16 warps.
// Warp w: head = w&3, js = w>>2. Per t, warp handles j = t*128 + js*32 + lane
// for ALL 8 i-rows. R/V/adj read DIRECTLY from gmem (L2-resident, no staging,
// no barriers inside the t-loop). p handed to agg phase via warp-private smem.
// Max-free softmax (e is O(1) bounded); mask -> p = 0 directly.
// ---------------------------------------------------------------------------
__global__ __launch_bounds__(512) void gat_main(
    const int*   __restrict__ adj,
    const float* __restrict__ a,
    const float* __restrict__ ln_g,
    const float* __restrict__ ln_b,
    float*       __restrict__ out)
{
    __shared__ float l_s[I_TILE * DIM];     // l rows (later: normalized agg buf)
    __shared__ float p_s[16 * I_TILE * 32]; // [warp][ii][j] (later: acc red buf)
    __shared__ float sl_s[16 * I_TILE];

    int tid  = threadIdx.x;
    int w    = tid >> 5, lane = tid & 31;
    int head = w & 3,    js   = w >> 2;      // js in 0..3
    int i0   = blockIdx.x * I_TILE;

    // 0.4 * a_d in registers (warp-uniform)
    float ar[32];
#pragma unroll
    for (int d = 0; d < 32; d++) ar[d] = 0.4f * __ldg(&a[d]);

    // stage l rows for this CTA (the only cross-warp shared data)
    for (int idx = tid; idx < I_TILE * DIM; idx += 512)
        l_s[idx] = g_L[i0 * DIM + idx];

    float la[I_TILE], sl[I_TILE], accA[I_TILE];
#pragma unroll
    for (int ii = 0; ii < I_TILE; ii++) {
        la[ii]   = __ldg(&g_La6[(i0 + ii) * HH + head]);
        sl[ii]   = 0.f;
        accA[ii] = 0.f;
    }
    __syncthreads();   // l_s visible

    const float4* Rt4 = reinterpret_cast<const float4*>(g_Rt);
    float* myp = &p_s[w * I_TILE * 32];

    for (int t = 0; t < 8; t++) {
        int j0   = t * 128;
        int jcol = j0 + js * 32 + lane;      // this lane's j

        // ---- front-batched loads (MLP ~17, all L2 hits) ----
        float4 r4[8];
#pragma unroll
        for (int q = 0; q < 8; q++)
            r4[q] = __ldg(&Rt4[(head * 8 + q) * NN + jcol]);
        float ra = __ldg(&g_Ra6[jcol * HH + head]);
        int adjv[I_TILE];
#pragma unroll
        for (int ii = 0; ii < I_TILE; ii++)
            adjv[ii] = __ldg(&adj[(i0 + ii) * NN + jcol]);

        // ---- e phase: p = mask ? exp(e) : 0 ----
#pragma unroll
        for (int ii = 0; ii < I_TILE; ii++) {
            const float4* lp = reinterpret_cast<const float4*>(&l_s[ii * DIM + head * 32]);
            float a0 = 0.f, a1 = 0.f, a2 = 0.f, a3 = 0.f;
#pragma unroll
            for (int q = 0; q < 8; q++) {
                float4 l4 = lp[q];
                a0 += ar[4 * q + 0] * fabsf(l4.x + r4[q].x);
                a1 += ar[4 * q + 1] * fabsf(l4.y + r4[q].y);
                a2 += ar[4 * q + 2] * fabsf(l4.z + r4[q].z);
                a3 += ar[4 * q + 3] * fabsf(l4.w + r4[q].w);
            }
            float e = la[ii] + ra + ((a0 + a1) + (a2 + a3));
            float p = adjv[ii] ? __expf(e) : 0.f;
            sl[ii] += p;
            myp[ii * 32 + lane] = p;
        }
        __syncwarp();

        // ---- agg phase: lane owns d; v direct from gmem (coalesced L2 hits) ----
#pragma unroll
        for (int q = 0; q < 4; q++) {
            int jrow = j0 + js * 32 + q * 8;
            const float* vp = &g_V[jrow * DIM + head * 32 + lane];
            float v0 = __ldg(vp + 0 * DIM), v1 = __ldg(vp + 1 * DIM);
            float v2 = __ldg(vp + 2 * DIM), v3 = __ldg(vp + 3 * DIM);
            float v4 = __ldg(vp + 4 * DIM), v5 = __ldg(vp + 5 * DIM);
            float v6 = __ldg(vp + 6 * DIM), v7 = __ldg(vp + 7 * DIM);
#pragma unroll
            for (int ii = 0; ii < I_TILE; ii++) {
                const float4* pp = reinterpret_cast<const float4*>(&myp[ii * 32 + q * 8]);
                float4 pA = pp[0], pB = pp[1];
                accA[ii] += pA.x * v0 + pA.y * v1 + pA.z * v2 + pA.w * v3
                          + pB.x * v4 + pB.y * v5 + pB.z * v6 + pB.w * v7;
            }
        }
        __syncwarp();
    }

    // ---- cross-warp (js) reduction ----
#pragma unroll
    for (int ii = 0; ii < I_TILE; ii++) {
        float S = sl[ii];
#pragma unroll
        for (int o = 16; o; o >>= 1) S += __shfl_xor_sync(0xffffffffu, S, o);
        sl[ii] = S;
    }
    __syncthreads();                 // everyone done with p_s as p-buffer
#pragma unroll
    for (int ii = 0; ii < I_TILE; ii++) {
        myp[ii * 32 + lane] = accA[ii];          // reuse p_s as acc buffer
        if (lane == 0) sl_s[w * I_TILE + ii] = sl[ii];
    }
    __syncthreads();

    // warp w: head' = w&3, covers ii = (w>>2) and (w>>2)+4
#pragma unroll
    for (int r = 0; r < 2; r++) {
        int ii = (w >> 2) + r * 4;
        int hh = w & 3;
        float acc = 0.f, S = 0.f;
#pragma unroll
        for (int g = 0; g < 4; g++) {
            acc += p_s[((g * 4 + hh) * I_TILE + ii) * 32 + lane];
            S   += sl_s[(g * 4 + hh) * I_TILE + ii];
        }
        l_s[ii * DIM + hh * 32 + lane] = acc * __frcp_rn(S);
    }
    __syncthreads();

    // LayerNorm + ReLU: warps 0..7 handle rows 0..7
    if (w < I_TILE) {
        int i = w;
        float v0 = l_s[i * DIM + lane];
        float v1 = l_s[i * DIM + 32 + lane];
        float v2 = l_s[i * DIM + 64 + lane];
        float v3 = l_s[i * DIM + 96 + lane];
        float sm = (v0 + v1) + (v2 + v3);
        float sq = v0 * v0 + v1 * v1 + v2 * v2 + v3 * v3;
#pragma unroll
        for (int o = 16; o; o >>= 1) {
            sm += __shfl_xor_sync(0xffffffffu, sm, o);
            sq += __shfl_xor_sync(0xffffffffu, sq, o);
        }
        float mean = sm * (1.f / 128.f);
        float var  = sq * (1.f / 128.f) - mean * mean;
        float rstd = rsqrtf(var + 1e-5f);
        float vals[4] = {v0, v1, v2, v3};
#pragma unroll
        for (int k = 0; k < 4; k++) {
            int c = 32 * k + lane;
            float y = (vals[k] - mean) * rstd * __ldg(&ln_g[c]) + __ldg(&ln_b[c]);
            out[(i0 + i) * DIM + c] = fmaxf(y, 0.f);
        }
    }
}

extern "C" void kernel_launch(void* const* d_in, const int* in_sizes, int n_in,
                              void* d_out, int out_size)
{
    const float* h   = (const float*)d_in[0];
    const int*   adj = (const int*)  d_in[1];
    const float* Wl  = (const float*)d_in[2];
    const float* Wr  = (const float*)d_in[3];
    const float* Wv  = (const float*)d_in[4];
    const float* a   = (const float*)d_in[5];
    const float* g   = (const float*)d_in[6];
    const float* b   = (const float*)d_in[7];

    prep_kernel<<<dim3(128, 3), 128>>>(h, Wl, Wr, Wv, a);
    gat_main<<<NN / I_TILE, 512>>>(adj, a, g, b, (float*)d_out);
}

// round 7
// speedup vs baseline: 2.3735x; 1.0468x over previous
#include <cuda_runtime.h>
#include <cuda_bf16.h>

#define NN 1024
#define DIM 128
#define HH 4
#define I_TILE 8
#define LOG2E 1.4426950408889634f

// Scratch (device globals: no allocations allowed)
__device__ float g_L[NN * DIM];
__device__ float g_Rt[NN * DIM];   // transposed: [head][q][j][4], d = q*4+c
__device__ float g_Vp[NN * DIM];   // paired:     [head][j/2][d][2]
__device__ float g_La6[NN * HH];   // 0.6*log2e * sum_d a_d*L   (exp2-ready)
__device__ float g_Ra6[NN * HH];

#define FMA2(acc, p, v) \
    asm("fma.rn.f32x2 %0, %1, %2, %3;" : "=l"(acc) : "l"(p), "l"(v), "l"(acc))

// ---------------------------------------------------------------------------
// Prep: L = h@W_l (row-major), Rt = transposed h@W_r, Vp = paired h@W_v,
// plus La6/Ra6 (pre-scaled by log2e for ex2-based softmax).
// Grid (256, 3), block 128. Each CTA: 4 rows x 128 cols.
// ---------------------------------------------------------------------------
__global__ __launch_bounds__(128) void prep_kernel(
    const float* __restrict__ h,
    const float* __restrict__ Wl,
    const float* __restrict__ Wr,
    const float* __restrict__ Wv,
    const float* __restrict__ a)
{
    int which = blockIdx.y;
    const float* W = (which == 0) ? Wl : (which == 1) ? Wr : Wv;
    int i0 = blockIdx.x * 4;
    int tid = threadIdx.x;

    __shared__ float h_s[4 * DIM];
#pragma unroll
    for (int q = 0; q < 4; q++)
        h_s[tid + q * 128] = h[i0 * DIM + tid + q * 128];
    __syncthreads();

    float acc[4] = {0.f, 0.f, 0.f, 0.f};
    const float4* h4 = reinterpret_cast<const float4*>(h_s);
#pragma unroll 8
    for (int k4 = 0; k4 < 32; k4++) {
        float w0 = __ldg(&W[(k4 * 4 + 0) * DIM + tid]);
        float w1 = __ldg(&W[(k4 * 4 + 1) * DIM + tid]);
        float w2 = __ldg(&W[(k4 * 4 + 2) * DIM + tid]);
        float w3 = __ldg(&W[(k4 * 4 + 3) * DIM + tid]);
#pragma unroll
        for (int r = 0; r < 4; r++) {
            float4 hv = h4[r * 32 + k4];
            acc[r] += hv.x * w0 + hv.y * w1 + hv.z * w2 + hv.w * w3;
        }
    }

    int head = tid >> 5, d = tid & 31;
    if (which == 0) {
#pragma unroll
        for (int r = 0; r < 4; r++) g_L[(i0 + r) * DIM + tid] = acc[r];
    } else if (which == 1) {
        // transposed store: (i, col=tid) -> g_Rt[((head*8+q)*NN + i)*4 + c]
        int q = d >> 2, c = d & 3;
        float* base = &g_Rt[(size_t)((head * 8 + q) * NN) * 4 + c];
#pragma unroll
        for (int r = 0; r < 4; r++) base[(i0 + r) * 4] = acc[r];
    } else {
        // paired store: {v[2k][d], v[2k+1][d]} at g_Vp[((head*512+k)*32+d)*2]
#pragma unroll
        for (int pr = 0; pr < 2; pr++) {
            float2 pv = make_float2(acc[2 * pr], acc[2 * pr + 1]);
            *reinterpret_cast<float2*>(
                &g_Vp[(size_t)((head * 512 + (i0 >> 1) + pr) * 32 + d) * 2]) = pv;
        }
    }

    if (which < 2) {
        float av = 0.6f * LOG2E * __ldg(&a[d]);
        float* A6 = (which == 0) ? g_La6 : g_Ra6;
#pragma unroll
        for (int r = 0; r < 4; r++) {
            float v = av * acc[r];
#pragma unroll
            for (int o = 16; o; o >>= 1) v += __shfl_xor_sync(0xffffffffu, v, o);
            if (d == 0) A6[(i0 + r) * HH + head] = v;
        }
    }
}

// ---------------------------------------------------------------------------
// Main fused kernel. Grid 128 (I_TILE=8 rows each), block 512 = 16 warps.
// Warp w: head = w&3, js = w>>2. Per t, warp handles j = t*128 + js*32 + lane
// for ALL 8 i-rows. R/Vp/adj read directly from gmem (L2-resident).
// e-phase: lane owns j; agg-phase: lane owns d with packed f32x2 FFMA2.
// Max-free softmax in base-2 (ar/la/ra pre-scaled by log2e); mask -> p = 0.
// ---------------------------------------------------------------------------
__global__ __launch_bounds__(512) void gat_main(
    const int*   __restrict__ adj,
    const float* __restrict__ a,
    const float* __restrict__ ln_g,
    const float* __restrict__ ln_b,
    float*       __restrict__ out)
{
    __shared__ __align__(16) float l_s[I_TILE * DIM];
    __shared__ __align__(16) float p_s[16 * I_TILE * 32];
    __shared__ float sl_s[16 * I_TILE];

    int tid  = threadIdx.x;
    int w    = tid >> 5, lane = tid & 31;
    int head = w & 3,    js   = w >> 2;      // js in 0..3
    int i0   = blockIdx.x * I_TILE;

    // 0.4*log2e * a_d in registers (warp-uniform)
    float ar[32];
#pragma unroll
    for (int d = 0; d < 32; d++) ar[d] = (0.4f * LOG2E) * __ldg(&a[d]);

    for (int idx = tid; idx < I_TILE * DIM; idx += 512)
        l_s[idx] = g_L[i0 * DIM + idx];

    float la[I_TILE], sl[I_TILE];
    unsigned long long acc2[I_TILE];
#pragma unroll
    for (int ii = 0; ii < I_TILE; ii++) {
        la[ii]   = __ldg(&g_La6[(i0 + ii) * HH + head]);
        sl[ii]   = 0.f;
        acc2[ii] = 0ull;                     // packed {0.f, 0.f}
    }
    __syncthreads();   // l_s visible

    const float4*  Rt4 = reinterpret_cast<const float4*>(g_Rt);
    const double*  Vp  = reinterpret_cast<const double*>(g_Vp);
    float* myp = &p_s[w * I_TILE * 32];

    for (int t = 0; t < 8; t++) {
        int j0   = t * 128;
        int jcol = j0 + js * 32 + lane;      // this lane's j

        // ---- front-batched loads (all L2 hits) ----
        float4 r4[8];
#pragma unroll
        for (int q = 0; q < 8; q++)
            r4[q] = __ldg(&Rt4[(head * 8 + q) * NN + jcol]);
        float ra = __ldg(&g_Ra6[jcol * HH + head]);
        int adjv[I_TILE];
#pragma unroll
        for (int ii = 0; ii < I_TILE; ii++)
            adjv[ii] = __ldg(&adj[(i0 + ii) * NN + jcol]);

        // ---- e phase: p = mask ? 2^e : 0 ----
#pragma unroll
        for (int ii = 0; ii < I_TILE; ii++) {
            const float4* lp = reinterpret_cast<const float4*>(&l_s[ii * DIM + head * 32]);
            float a0 = 0.f, a1 = 0.f, a2 = 0.f, a3 = 0.f;
#pragma unroll
            for (int q = 0; q < 8; q++) {
                float4 l4 = lp[q];
                a0 += ar[4 * q + 0] * fabsf(l4.x + r4[q].x);
                a1 += ar[4 * q + 1] * fabsf(l4.y + r4[q].y);
                a2 += ar[4 * q + 2] * fabsf(l4.z + r4[q].z);
                a3 += ar[4 * q + 3] * fabsf(l4.w + r4[q].w);
            }
            float e = la[ii] + ra + ((a0 + a1) + (a2 + a3));
            float p;
            asm("ex2.approx.f32 %0, %1;" : "=f"(p) : "f"(e));
            p = adjv[ii] ? p : 0.f;
            sl[ii] += p;
            myp[ii * 32 + lane] = p;
        }
        __syncwarp();

        // ---- agg phase: lane owns d; packed pairs over j, FFMA2 ----
        int jp0 = (j0 + js * 32) >> 1;       // j-pair base for this warp
#pragma unroll
        for (int q = 0; q < 4; q++) {
            const double* vp = &Vp[(size_t)(head * 512 + jp0 + q * 4) * 32 + lane];
            unsigned long long v0 = __double_as_longlong(__ldg(vp + 0 * 32));
            unsigned long long v1 = __double_as_longlong(__ldg(vp + 1 * 32));
            unsigned long long v2 = __double_as_longlong(__ldg(vp + 2 * 32));
            unsigned long long v3 = __double_as_longlong(__ldg(vp + 3 * 32));
#pragma unroll
            for (int ii = 0; ii < I_TILE; ii++) {
                ulonglong2 pA = *reinterpret_cast<const ulonglong2*>(&myp[ii * 32 + q * 8]);
                ulonglong2 pB = *reinterpret_cast<const ulonglong2*>(&myp[ii * 32 + q * 8 + 4]);
                FMA2(acc2[ii], pA.x, v0);
                FMA2(acc2[ii], pA.y, v1);
                FMA2(acc2[ii], pB.x, v2);
                FMA2(acc2[ii], pB.y, v3);
            }
        }
        __syncwarp();
    }

    // ---- horizontal unpack of packed accumulators ----
    float accA[I_TILE];
#pragma unroll
    for (int ii = 0; ii < I_TILE; ii++) {
        float lo, hi;
        asm("mov.b64 {%0, %1}, %2;" : "=f"(lo), "=f"(hi) : "l"(acc2[ii]));
        accA[ii] = lo + hi;
    }

    // ---- cross-warp (js) reduction ----
#pragma unroll
    for (int ii = 0; ii < I_TILE; ii++) {
        float S = sl[ii];
#pragma unroll
        for (int o = 16; o; o >>= 1) S += __shfl_xor_sync(0xffffffffu, S, o);
        sl[ii] = S;
    }
    __syncthreads();                 // everyone done with p_s as p-buffer
#pragma unroll
    for (int ii = 0; ii < I_TILE; ii++) {
        myp[ii * 32 + lane] = accA[ii];          // reuse p_s as acc buffer
        if (lane == 0) sl_s[w * I_TILE + ii] = sl[ii];
    }
    __syncthreads();

    // warp w: head' = w&3, covers ii = (w>>2) and (w>>2)+4
#pragma unroll
    for (int r = 0; r < 2; r++) {
        int ii = (w >> 2) + r * 4;
        int hh = w & 3;
        float acc = 0.f, S = 0.f;
#pragma unroll
        for (int g = 0; g < 4; g++) {
            acc += p_s[((g * 4 + hh) * I_TILE + ii) * 32 + lane];
            S   += sl_s[(g * 4 + hh) * I_TILE + ii];
        }
        l_s[ii * DIM + hh * 32 + lane] = acc * __frcp_rn(S);
    }
    __syncthreads();

    // LayerNorm + ReLU: warps 0..7 handle rows 0..7
    if (w < I_TILE) {
        int i = w;
        float v0 = l_s[i * DIM + lane];
        float v1 = l_s[i * DIM + 32 + lane];
        float v2 = l_s[i * DIM + 64 + lane];
        float v3 = l_s[i * DIM + 96 + lane];
        float sm = (v0 + v1) + (v2 + v3);
        float sq = v0 * v0 + v1 * v1 + v2 * v2 + v3 * v3;
#pragma unroll
        for (int o = 16; o; o >>= 1) {
            sm += __shfl_xor_sync(0xffffffffu, sm, o);
            sq += __shfl_xor_sync(0xffffffffu, sq, o);
        }
        float mean = sm * (1.f / 128.f);
        float var  = sq * (1.f / 128.f) - mean * mean;
        float rstd = rsqrtf(var + 1e-5f);
        float vals[4] = {v0, v1, v2, v3};
#pragma unroll
        for (int k = 0; k < 4; k++) {
            int c = 32 * k + lane;
            float y = (vals[k] - mean) * rstd * __ldg(&ln_g[c]) + __ldg(&ln_b[c]);
            out[(i0 + i) * DIM + c] = fmaxf(y, 0.f);
        }
    }
}

extern "C" void kernel_launch(void* const* d_in, const int* in_sizes, int n_in,
                              void* d_out, int out_size)
{
    const float* h   = (const float*)d_in[0];
    const int*   adj = (const int*)  d_in[1];
    const float* Wl  = (const float*)d_in[2];
    const float* Wr  = (const float*)d_in[3];
    const float* Wv  = (const float*)d_in[4];
    const float* a   = (const float*)d_in[5];
    const float* g   = (const float*)d_in[6];
    const float* b   = (const float*)d_in[7];

    prep_kernel<<<dim3(256, 3), 128>>>(h, Wl, Wr, Wv, a);
    gat_main<<<NN / I_TILE, 512>>>(adj, a, g, b, (float*)d_out);
}